// round 12
// baseline (speedup 1.0000x reference)
#include <cuda_runtime.h>
#include <cstdint>

#define EPS_F 1e-6f
#define S_DIM 2048
#define H_DIM 12
#define W_DIM 32
#define MAXSEG 33
#define PLANE ((size_t)S_DIM * S_DIM)

// ---------------------------------------------------------------------------
// Single kernel. Per-block lightweight setup:
//   * threads <32 : hinge = -b1/w1 per unit, rank-sort (values + unit indices)
//   * threads <12 : prefix-scan of piecewise-linear (slope, intercept) across
//                   segments: crossing a hinge adds (w1>0) or removes (w1<0)
//                   one unit's contribution. O(W + nseg) per head.
// Main: 4 contiguous j per thread, nd via __logf (no tables), one bracketed
// hinge search, 12 float4 streaming stores (one per head plane).
// ---------------------------------------------------------------------------
__global__ __launch_bounds__(256, 6) void fire_all(
        const float* __restrict__ w1,
        const float* __restrict__ b1,
        const float* __restrict__ w2,
        const float* __restrict__ b2,
        const float* __restrict__ cp,
        const float* __restrict__ lmp,
        const float* __restrict__ ilp,
        float* __restrict__ out) {
    __shared__ float shW1[W_DIM], shB1[W_DIM], shT[W_DIM];
    __shared__ float shH[W_DIM + 1];
    __shared__ int   shIdx[W_DIM + 1];
    __shared__ int   shNh;
    __shared__ float s_hinge[MAXSEG];
    __shared__ float s_slope[MAXSEG * H_DIM];
    __shared__ float s_icpt [MAXSEG * H_DIM];

    const float INFF = __int_as_float(0x7f800000);
    const int t = threadIdx.x;

    const float c   = __ldg(cp);
    const float thr = fabsf(__ldg(lmp) * __ldg(ilp));

    // ---- hinge positions + rank sort (with unit indices) ----
    if (t < W_DIM) { shW1[t] = w1[t]; shB1[t] = b1[t]; }
    __syncthreads();
    if (t < W_DIM) {
        bool valid = (shW1[t] != 0.0f);            // w1==0 -> no hinge
        shT[t] = valid ? (-shB1[t] / shW1[t]) : INFF;
    }
    __syncthreads();
    if (t < W_DIM) {
        float tv = shT[t];
        int rank = 0;
        #pragma unroll
        for (int v = 0; v < W_DIM; v++) {
            float o = shT[v];
            rank += (o < tv) || (o == tv && v < t);
        }
        shH[rank] = tv;
        shIdx[rank] = t;
        if (t == 0) {
            int n = 0;
            for (int v = 0; v < W_DIM; v++) n += (shW1[v] != 0.0f);
            shNh = n;
        }
    }
    __syncthreads();
    const int nh = shNh;
    if (t < MAXSEG) s_hinge[t] = (t < nh) ? shH[t] : INFF;   // +inf padded

    // ---- coefficient prefix scan: thread t = head t ----
    if (t < H_DIM) {
        const float* w2row = w2 + t * W_DIM;
        // segment 0 (nd -> -inf): active = {w1<0} u {w1==0 && b1>0}
        float sl = 0.0f, ic = __ldg(&b2[t]);
        #pragma unroll
        for (int w = 0; w < W_DIM; w++) {
            float w1v = shW1[w], b1v = shB1[w];
            bool act0 = (w1v < 0.0f) || (w1v == 0.0f && b1v > 0.0f);
            if (act0) {
                float w2v = __ldg(&w2row[w]);
                sl = fmaf(w2v, w1v, sl);
                ic = fmaf(w2v, b1v, ic);
            }
        }
        s_slope[t] = sl;
        s_icpt [t] = ic;
        for (int s = 1; s <= nh; s++) {
            int   u   = shIdx[s - 1];              // unit whose hinge we cross
            float w1v = shW1[u], b1v = shB1[u];
            float w2v = __ldg(&w2row[u]);
            if (w1v > 0.0f) {                      // becomes active
                sl = fmaf( w2v, w1v, sl);
                ic = fmaf( w2v, b1v, ic);
            } else {                               // becomes inactive
                sl = fmaf(-w2v, w1v, sl);
                ic = fmaf(-w2v, b1v, ic);
            }
            s_slope[s * H_DIM + t] = sl;
            s_icpt [s * H_DIM + t] = ic;
        }
    }
    __syncthreads();

    // ---- main fill ----
    const int i  = blockIdx.y;
    const int j0 = blockIdx.x * 1024 + t * 4;

    float pos_norm = fmaxf((float)i, thr) + EPS_F;
    float invB = __frcp_rn(__logf(fabsf(c * pos_norm) + 1.0f + EPS_F));

    float nd[4];
    #pragma unroll
    for (int k = 0; k < 4; k++) {
        float abs_rel = (float)abs(i - (j0 + k)) + EPS_F;
        nd[k] = __logf(abs_rel * c + 1.0f + EPS_F) * invB;
    }

    // bracket the contiguous window (handles V-shape at diagonal too)
    float ndlo = fminf(fminf(nd[0], nd[1]), fminf(nd[2], nd[3]));
    float ndhi = fmaxf(fmaxf(nd[0], nd[1]), fmaxf(nd[2], nd[3]));

    // one lower_bound over 32 sorted (+inf padded) hinges
    int lo = 0, hi = 32;
    #pragma unroll
    for (int it = 0; it < 5; it++) {
        int mid = (lo + hi) >> 1;
        bool ge = (ndlo >= s_hinge[mid]);
        lo = ge ? mid + 1 : lo;
        hi = ge ? hi : mid;
    }
    const int seg = lo;
    const bool uni = (ndhi < s_hinge[seg]);   // whole window inside one segment

    const size_t base = (size_t)i * S_DIM + j0;
    if (uni) {
        const float* sl = &s_slope[seg * H_DIM];
        const float* ic = &s_icpt [seg * H_DIM];
        float* p = out + base;
        #pragma unroll
        for (int h = 0; h < H_DIM; h++) {
            float s = sl[h], bb = ic[h];
            float4 v;
            v.x = fmaf(nd[0], s, bb);
            v.y = fmaf(nd[1], s, bb);
            v.z = fmaf(nd[2], s, bb);
            v.w = fmaf(nd[3], s, bb);
            __stcs(reinterpret_cast<float4*>(p), v);
            p += PLANE;
        }
    } else {
        // rare: window crosses a hinge -> per-element segment
        int sg[4];
        #pragma unroll
        for (int k = 0; k < 4; k++) {
            int l2 = 0, h2 = 32;
            #pragma unroll
            for (int it = 0; it < 5; it++) {
                int mid = (l2 + h2) >> 1;
                bool ge = (nd[k] >= s_hinge[mid]);
                l2 = ge ? mid + 1 : l2;
                h2 = ge ? h2 : mid;
            }
            sg[k] = l2 * H_DIM;
        }
        float* p = out + base;
        #pragma unroll
        for (int h = 0; h < H_DIM; h++) {
            float4 v;
            v.x = fmaf(nd[0], s_slope[sg[0] + h], s_icpt[sg[0] + h]);
            v.y = fmaf(nd[1], s_slope[sg[1] + h], s_icpt[sg[1] + h]);
            v.z = fmaf(nd[2], s_slope[sg[2] + h], s_icpt[sg[2] + h]);
            v.w = fmaf(nd[3], s_slope[sg[3] + h], s_icpt[sg[3] + h]);
            __stcs(reinterpret_cast<float4*>(p), v);
            p += PLANE;
        }
    }
}

// ---------------------------------------------------------------------------
// Inputs (metadata order): x, w1, b1, w2, b2, c, L_multiplier, init_L
// ---------------------------------------------------------------------------
extern "C" void kernel_launch(void* const* d_in, const int* in_sizes, int n_in,
                              void* d_out, int out_size) {
    const float* w1 = (const float*)d_in[1];
    const float* b1 = (const float*)d_in[2];
    const float* w2 = (const float*)d_in[3];
    const float* b2 = (const float*)d_in[4];
    const float* c  = (const float*)d_in[5];
    const float* lm = (const float*)d_in[6];
    const float* il = (const float*)d_in[7];
    float* out = (float*)d_out;

    dim3 grid(S_DIM / 1024, S_DIM);   // (2, 2048)
    fire_all<<<grid, 256>>>(w1, b1, w2, b2, c, lm, il, out);
}

// round 14
// speedup vs baseline: 1.1669x; 1.1669x over previous
#include <cuda_runtime.h>
#include <cstdint>

#define EPS_F 1e-6f
#define S_DIM 2048
#define H_DIM 12
#define W_DIM 32
#define MAXSEG 33
#define PLANE ((size_t)S_DIM * S_DIM)

// -------- persistent scratch (device globals: no allocation allowed) --------
__device__ float g_hinge[MAXSEG];   // sorted hinges, +inf padded (33 entries)
__device__ float g_slope[MAXSEG * H_DIM];
__device__ float g_icpt [MAXSEG * H_DIM];

// ---------------------------------------------------------------------------
// Setup: 33 blocks x 64 threads. Block b computes segment b's 12 coefficients
// (O(W) active-unit sum); block 0 also publishes the sorted hinge array.
// Triggers PDL immediately so the main kernel can launch concurrently.
// ---------------------------------------------------------------------------
__global__ __launch_bounds__(64) void fire_setup(
        const float* __restrict__ w1, const float* __restrict__ b1,
        const float* __restrict__ w2, const float* __restrict__ b2) {
    cudaTriggerProgrammaticLaunchCompletion();

    __shared__ float shW1[W_DIM], shB1[W_DIM], shT[W_DIM], shH[W_DIM + 1];
    __shared__ int   shNh;
    const float INFF = __int_as_float(0x7f800000);
    const int t = threadIdx.x;
    const int b = blockIdx.x;

    if (t < W_DIM) { shW1[t] = w1[t]; shB1[t] = b1[t]; }
    __syncthreads();
    if (t < W_DIM) {
        bool valid = (shW1[t] != 0.0f);            // w1==0 -> no hinge
        shT[t] = valid ? (-shB1[t] / shW1[t]) : INFF;
    }
    __syncthreads();
    if (t < W_DIM) {
        float tv = shT[t];
        int rank = 0;
        #pragma unroll
        for (int v = 0; v < W_DIM; v++) {
            float o = shT[v];
            rank += (o < tv) || (o == tv && v < t);
        }
        shH[rank] = tv;
        if (t == 0) {
            int n = 0;
            for (int v = 0; v < W_DIM; v++) n += (shW1[v] != 0.0f);
            shNh = n;
        }
    }
    __syncthreads();
    const int nh = shNh;
    if (b == 0 && t < MAXSEG) g_hinge[t] = (t < nh) ? shH[t] : INFF;

    if (b <= nh && t < H_DIM) {
        float x;                                    // interior point of segment b
        if (nh == 0)      x = 0.0f;
        else if (b == 0)  x = shH[0] - 1.0f;
        else if (b == nh) x = shH[nh - 1] + 1.0f;
        else              x = 0.5f * (shH[b - 1] + shH[b]);

        float sl = 0.0f, ic = __ldg(&b2[t]);
        #pragma unroll
        for (int w = 0; w < W_DIM; w++) {
            float w1v = shW1[w], b1v = shB1[w];
            if (w1v * x + b1v > 0.0f) {             // unit active on this segment
                float w2v = __ldg(&w2[t * W_DIM + w]);
                sl = fmaf(w2v, w1v, sl);
                ic = fmaf(w2v, b1v, ic);
            }
        }
        g_slope[b * H_DIM + t] = sl;
        g_icpt [b * H_DIM + t] = ic;
    }
}

// ---------------------------------------------------------------------------
// Main fill: grid (2, 2048), 256 threads, 4 CONTIGUOUS j per thread.
// Phase A (independent of setup): nd via __logf, bracket min/max.
// Phase B (after griddep sync): coeffs -> smem, one bracketed hinge search,
// 12 plain float4 stores (L2-resident across graph replays).
// ---------------------------------------------------------------------------
__global__ __launch_bounds__(256) void fire_main(
        const float* __restrict__ cp,
        const float* __restrict__ lmp,
        const float* __restrict__ ilp,
        float* __restrict__ out) {
    __shared__ float s_hinge[MAXSEG];
    __shared__ float s_slope[MAXSEG * H_DIM];
    __shared__ float s_icpt [MAXSEG * H_DIM];

    const int tid = threadIdx.x;
    const int i   = blockIdx.y;
    const int j0  = blockIdx.x * 1024 + tid * 4;

    // ---- Phase A: nd math, independent of setup results ----
    const float c   = __ldg(cp);
    const float thr = fabsf(__ldg(lmp) * __ldg(ilp));

    float pos_norm = fmaxf((float)i, thr) + EPS_F;
    float invB = __frcp_rn(__logf(fabsf(c * pos_norm) + 1.0f + EPS_F));

    float nd[4];
    #pragma unroll
    for (int k = 0; k < 4; k++) {
        float abs_rel = (float)abs(i - (j0 + k)) + EPS_F;
        nd[k] = __logf(abs_rel * c + 1.0f + EPS_F) * invB;
    }
    float ndlo = fminf(fminf(nd[0], nd[1]), fminf(nd[2], nd[3]));
    float ndhi = fmaxf(fmaxf(nd[0], nd[1]), fmaxf(nd[2], nd[3]));

    // ---- Phase B: wait for setup grid, then consume its tables ----
    cudaGridDependencySynchronize();

    for (int idx = tid; idx < MAXSEG * H_DIM; idx += 256) {
        s_slope[idx] = g_slope[idx];
        s_icpt [idx] = g_icpt [idx];
    }
    if (tid < MAXSEG) s_hinge[tid] = g_hinge[tid];
    __syncthreads();

    // one lower_bound over 32 sorted (+inf padded) hinges
    int lo = 0, hi = 32;
    #pragma unroll
    for (int it = 0; it < 5; it++) {
        int mid = (lo + hi) >> 1;
        bool ge = (ndlo >= s_hinge[mid]);
        lo = ge ? mid + 1 : lo;
        hi = ge ? hi : mid;
    }
    const int seg = lo;
    const bool uni = (ndhi < s_hinge[seg]);   // whole window inside one segment

    const size_t base = (size_t)i * S_DIM + j0;
    if (uni) {
        const float* sl = &s_slope[seg * H_DIM];
        const float* ic = &s_icpt [seg * H_DIM];
        float* p = out + base;
        #pragma unroll
        for (int h = 0; h < H_DIM; h++) {
            float s = sl[h], bb = ic[h];
            float4 v;
            v.x = fmaf(nd[0], s, bb);
            v.y = fmaf(nd[1], s, bb);
            v.z = fmaf(nd[2], s, bb);
            v.w = fmaf(nd[3], s, bb);
            *reinterpret_cast<float4*>(p) = v;    // plain store: L2-resident
            p += PLANE;
        }
    } else {
        // rare: window crosses a hinge -> per-element segment
        int sg[4];
        #pragma unroll
        for (int k = 0; k < 4; k++) {
            int l2 = 0, h2 = 32;
            #pragma unroll
            for (int it = 0; it < 5; it++) {
                int mid = (l2 + h2) >> 1;
                bool ge = (nd[k] >= s_hinge[mid]);
                l2 = ge ? mid + 1 : l2;
                h2 = ge ? h2 : mid;
            }
            sg[k] = l2 * H_DIM;
        }
        float* p = out + base;
        #pragma unroll
        for (int h = 0; h < H_DIM; h++) {
            float4 v;
            v.x = fmaf(nd[0], s_slope[sg[0] + h], s_icpt[sg[0] + h]);
            v.y = fmaf(nd[1], s_slope[sg[1] + h], s_icpt[sg[1] + h]);
            v.z = fmaf(nd[2], s_slope[sg[2] + h], s_icpt[sg[2] + h]);
            v.w = fmaf(nd[3], s_slope[sg[3] + h], s_icpt[sg[3] + h]);
            *reinterpret_cast<float4*>(p) = v;
            p += PLANE;
        }
    }
}

// ---------------------------------------------------------------------------
// Inputs (metadata order): x, w1, b1, w2, b2, c, L_multiplier, init_L
// ---------------------------------------------------------------------------
extern "C" void kernel_launch(void* const* d_in, const int* in_sizes, int n_in,
                              void* d_out, int out_size) {
    const float* w1 = (const float*)d_in[1];
    const float* b1 = (const float*)d_in[2];
    const float* w2 = (const float*)d_in[3];
    const float* b2 = (const float*)d_in[4];
    const float* c  = (const float*)d_in[5];
    const float* lm = (const float*)d_in[6];
    const float* il = (const float*)d_in[7];
    float* out = (float*)d_out;

    fire_setup<<<MAXSEG, 64>>>(w1, b1, w2, b2);

    // PDL: main may launch while setup is still running; it synchronizes
    // on the setup grid via cudaGridDependencySynchronize() before reading
    // the coefficient tables.
    cudaLaunchConfig_t cfg = {};
    cfg.gridDim  = dim3(S_DIM / 1024, S_DIM);   // (2, 2048)
    cfg.blockDim = dim3(256);
    cfg.stream   = 0;
    cudaLaunchAttribute attr[1];
    attr[0].id = cudaLaunchAttributeProgrammaticStreamSerialization;
    attr[0].val.programmaticStreamSerializationAllowed = 1;
    cfg.attrs    = attr;
    cfg.numAttrs = 1;
    cudaLaunchKernelEx(&cfg, fire_main, (const float*)d_in[5],
                       (const float*)d_in[6], (const float*)d_in[7], out);
}